// round 12
// baseline (speedup 1.0000x reference)
#include <cuda_runtime.h>
#include <cuda_bf16.h>
#include <math.h>

// ---------------------------------------------------------------------------
// MS-SSIM, 16x3x512x512 fp32, 5 levels.
// v3b: v3 with pyramid smem pitch fixed to 68 floats (16B-aligned rows for
// float4). (1) hierarchical pyramid-build kernel, (2) single SSIM kernel for
// all 5 levels (bid-range dispatch), (3) f32x2 packed separable conv,
// launch_bounds(256,4).
// ---------------------------------------------------------------------------

#define NC 48

typedef unsigned long long u64;

// ---- f32x2 packed helpers (sm_103a) ----
__device__ __forceinline__ u64 pack2(float lo, float hi) {
    u64 r; asm("mov.b64 %0, {%1,%2};" : "=l"(r) : "f"(lo), "f"(hi)); return r;
}
__device__ __forceinline__ void unpack2(u64 v, float& lo, float& hi) {
    asm("mov.b64 {%0,%1}, %2;" : "=f"(lo), "=f"(hi) : "l"(v));
}
__device__ __forceinline__ u64 fma2(u64 a, u64 b, u64 c) {
    u64 d; asm("fma.rn.f32x2 %0, %1, %2, %3;" : "=l"(d) : "l"(a), "l"(b), "l"(c)); return d;
}
__device__ __forceinline__ u64 mul2(u64 a, u64 b) {
    u64 d; asm("mul.rn.f32x2 %0, %1, %2;" : "=l"(d) : "l"(a), "l"(b)); return d;
}
__device__ __forceinline__ u64 add2(u64 a, u64 b) {
    u64 d; asm("add.rn.f32x2 %0, %1, %2;" : "=l"(d) : "l"(a), "l"(b)); return d;
}
__device__ __forceinline__ u64 bcast2(float w) {
    unsigned u = __float_as_uint(w);
    return ((u64)u << 32) | (u64)u;
}

// Normalized 1-D Gaussian, sigma=1.5, ws=11 (symmetric: 6 distinct values).
__device__ __forceinline__ constexpr float GW(int k) {
    constexpr float g[6] = {
        0.00102838f, 0.00759873f, 0.03600081f, 0.10936079f, 0.21300570f,
        0.26601192f };
    return g[k <= 5 ? k : 10 - k];
}

// Pyramid scratch, levels 1..4, both images.
__device__ float g_pyr1[4177920];
__device__ float g_pyr2[4177920];
__device__ float g_acc[10];   // [2l]=sum(ssim), [2l+1]=sum(cs)

#define L1OFF 0
#define L2OFF 3145728      // + 48*256*256
#define L3OFF 3932160      // + 48*128*128
#define L4OFF 4128768      // + 48*64*64

// ---------------------------------------------------------------------------
// Pyramid build: each block owns one 64x64 region of one image pair and
// produces the corresponding 32x32 / 16x16 / 8x8 / 4x4 mean-pool outputs
// (iterated 2x2 means == reference's chained _avg_pool2). Grid = 48*64.
// ---------------------------------------------------------------------------
__global__ void __launch_bounds__(256) pyramid_kernel(
    const float* __restrict__ img1, const float* __restrict__ img2,
    float* __restrict__ pyr1, float* __restrict__ pyr2)
{
    // pitch 68 floats = 272 bytes (16B-aligned rows for float4 stores)
    __shared__ __align__(16) float s[2][64][68];
    __shared__ float p1[2][32][33];
    __shared__ float p2[2][16][17];
    __shared__ float p3[2][8][9];

    const int tid = threadIdx.x;
    const int bid = blockIdx.x;
    if (bid == 0 && tid < 10) g_acc[tid] = 0.0f;

    const int z  = bid >> 6;
    const int r  = bid & 63;
    const int ry = r >> 3, rx = r & 7;

    const float* b1 = img1 + (size_t)z * 512 * 512 + (size_t)ry * 64 * 512 + rx * 64;
    const float* b2 = img2 + (size_t)z * 512 * 512 + (size_t)ry * 64 * 512 + rx * 64;

    // load 64x64 region of both images (float4; gmem and smem 16B-aligned)
    #pragma unroll
    for (int it = 0; it < 4; it++) {
        int i = tid + it * 256;           // 1024 float4 per image
        int row = i >> 4, c4 = (i & 15) * 4;
        float4 v1 = *(const float4*)(b1 + (size_t)row * 512 + c4);
        float4 v2 = *(const float4*)(b2 + (size_t)row * 512 + c4);
        *(float4*)&s[0][row][c4] = v1;
        *(float4*)&s[1][row][c4] = v2;
    }
    __syncthreads();

    // level 1: 32x32
    #pragma unroll
    for (int it = 0; it < 4; it++) {
        int i = tid + it * 256;
        int oy = i >> 5, ox = i & 31;
        #pragma unroll
        for (int im = 0; im < 2; im++) {
            float v = 0.25f * ((s[im][2*oy][2*ox]   + s[im][2*oy][2*ox+1]) +
                               (s[im][2*oy+1][2*ox] + s[im][2*oy+1][2*ox+1]));
            p1[im][oy][ox] = v;
            float* dst = (im == 0 ? pyr1 : pyr2) + L1OFF;
            dst[(size_t)z * 65536 + (size_t)(ry*32 + oy) * 256 + rx*32 + ox] = v;
        }
    }
    __syncthreads();

    // level 2: 16x16
    {
        int oy = tid >> 4, ox = tid & 15;
        #pragma unroll
        for (int im = 0; im < 2; im++) {
            float v = 0.25f * ((p1[im][2*oy][2*ox]   + p1[im][2*oy][2*ox+1]) +
                               (p1[im][2*oy+1][2*ox] + p1[im][2*oy+1][2*ox+1]));
            p2[im][oy][ox] = v;
            float* dst = (im == 0 ? pyr1 : pyr2) + L2OFF;
            dst[(size_t)z * 16384 + (size_t)(ry*16 + oy) * 128 + rx*16 + ox] = v;
        }
    }
    __syncthreads();

    // level 3: 8x8
    if (tid < 64) {
        int oy = tid >> 3, ox = tid & 7;
        #pragma unroll
        for (int im = 0; im < 2; im++) {
            float v = 0.25f * ((p2[im][2*oy][2*ox]   + p2[im][2*oy][2*ox+1]) +
                               (p2[im][2*oy+1][2*ox] + p2[im][2*oy+1][2*ox+1]));
            p3[im][oy][ox] = v;
            float* dst = (im == 0 ? pyr1 : pyr2) + L3OFF;
            dst[(size_t)z * 4096 + (size_t)(ry*8 + oy) * 64 + rx*8 + ox] = v;
        }
    }
    __syncthreads();

    // level 4: 4x4
    if (tid < 16) {
        int oy = tid >> 2, ox = tid & 3;
        #pragma unroll
        for (int im = 0; im < 2; im++) {
            float v = 0.25f * ((p3[im][2*oy][2*ox]   + p3[im][2*oy][2*ox+1]) +
                               (p3[im][2*oy+1][2*ox] + p3[im][2*oy+1][2*ox+1]));
            float* dst = (im == 0 ? pyr1 : pyr2) + L4OFF;
            dst[(size_t)z * 1024 + (size_t)(ry*4 + oy) * 32 + rx*4 + ox] = v;
        }
    }
}

// ---------------------------------------------------------------------------
// SSIM for all 5 levels in one launch. 1D grid; bid range selects level.
// Blocks per level: L0 16x16x48=12288, L1 8x8x48=3072, L2 4x4x48=768,
// L3 2x2x48=192, L4 1x1x48=48. Total 16368.
// ---------------------------------------------------------------------------
__global__ void __launch_bounds__(256, 4) ssim_all_kernel(
    const float* __restrict__ img1, const float* __restrict__ img2,
    const float* __restrict__ pyr1, const float* __restrict__ pyr2)
{
    __shared__ __align__(16) float sx[42][44];
    __shared__ __align__(16) float sy[42][44];
    __shared__ __align__(16) float q[5][42][34];
    __shared__ float red[16];

    const int tid = threadIdx.x;
    const int bid = blockIdx.x;

    // ---- level dispatch ----
    const int lev = (bid >= 12288) + (bid >= 15360) + (bid >= 16128) + (bid >= 16320);
    const int base = lev == 0 ? 0 : lev == 1 ? 12288 : lev == 2 ? 15360
                   : lev == 3 ? 16128 : 16320;
    const int lsh = 4 - lev;                 // gx = 1 << lsh
    const int S = 512 >> lev;
    const int OUT = S - 10;

    const int local = bid - base;
    const int z  = local >> (2 * lsh);
    const int rem = local & ((1 << (2 * lsh)) - 1);
    const int by = rem >> lsh;
    const int bx = rem & ((1 << lsh) - 1);

    const float* xl;
    const float* yl;
    if (lev == 0)      { xl = img1;         yl = img2; }
    else if (lev == 1) { xl = pyr1 + L1OFF; yl = pyr2 + L1OFF; }
    else if (lev == 2) { xl = pyr1 + L2OFF; yl = pyr2 + L2OFF; }
    else if (lev == 3) { xl = pyr1 + L3OFF; yl = pyr2 + L3OFF; }
    else               { xl = pyr1 + L4OFF; yl = pyr2 + L4OFF; }

    const int tileX = bx * 32;
    const int tileY = by * 32;
    const float* xb = xl + (size_t)z * S * S;
    const float* yb = yl + (size_t)z * S * S;

    // ---------------- Phase A: load 42x42 tile (zero-pad OOB) -------------
    #pragma unroll
    for (int it = 0; it < 7; it++) {
        int i = tid + it * 256;
        if (i < 42 * 42) {
            int r = i / 42, c = i - r * 42;
            int gr = tileY + r, gc = tileX + c;
            float vx = 0.0f, vy = 0.0f;
            if (gr < S && gc < S) {
                vx = xb[(size_t)gr * S + gc];
                vy = yb[(size_t)gr * S + gc];
            }
            sx[r][c] = vx;
            sy[r][c] = vy;
        }
    }
    __syncthreads();

    // ---------------- Phase B: vertical conv, packed cols -----------------
    if (tid < 168) {
        const int pc = tid % 21;
        const int rb = (tid / 21) * 4;
        const int c2 = 2 * pc;

        u64 acc[5][4];
        #pragma unroll
        for (int ch = 0; ch < 5; ch++)
            #pragma unroll
            for (int i = 0; i < 4; i++) acc[ch][i] = 0ull;

        #pragma unroll
        for (int w = 0; w < 14; w++) {
            u64 xv = *(const u64*)&sx[rb + w][c2];
            u64 yv = *(const u64*)&sy[rb + w][c2];
            u64 p[5];
            p[0] = xv;
            p[1] = yv;
            p[2] = mul2(xv, xv);
            p[3] = mul2(yv, yv);
            p[4] = mul2(xv, yv);
            #pragma unroll
            for (int i = 0; i < 4; i++) {
                const int k = w - i;
                if (k >= 0 && k <= 10) {
                    const u64 g2 = bcast2(GW(k));
                    #pragma unroll
                    for (int ch = 0; ch < 5; ch++)
                        acc[ch][i] = fma2(p[ch], g2, acc[ch][i]);
                }
            }
        }
        #pragma unroll
        for (int ch = 0; ch < 5; ch++) {
            #pragma unroll
            for (int j = 0; j < 2; j++) {
                float a0lo, a0hi, a1lo, a1hi;
                unpack2(acc[ch][2*j],     a0lo, a0hi);
                unpack2(acc[ch][2*j + 1], a1lo, a1hi);
                *(u64*)&q[ch][c2    ][rb + 2*j] = pack2(a0lo, a1lo);
                *(u64*)&q[ch][c2 + 1][rb + 2*j] = pack2(a0hi, a1hi);
            }
        }
    }
    __syncthreads();

    // ---------------- Phase C: horizontal conv + epilogue -----------------
    const int pr = tid & 15;
    const int c0 = (tid >> 4) * 2;

    u64 acc[5][2];
    #pragma unroll
    for (int ch = 0; ch < 5; ch++) { acc[ch][0] = 0ull; acc[ch][1] = 0ull; }

    #pragma unroll
    for (int k = 0; k < 12; k++) {
        u64 v[5];
        #pragma unroll
        for (int ch = 0; ch < 5; ch++)
            v[ch] = *(const u64*)&q[ch][c0 + k][2 * pr];
        if (k <= 10) {
            const u64 g2 = bcast2(GW(k));
            #pragma unroll
            for (int ch = 0; ch < 5; ch++)
                acc[ch][0] = fma2(v[ch], g2, acc[ch][0]);
        }
        if (k >= 1) {
            const u64 g2 = bcast2(GW(k - 1));
            #pragma unroll
            for (int ch = 0; ch < 5; ch++)
                acc[ch][1] = fma2(v[ch], g2, acc[ch][1]);
        }
    }

    // ---- SSIM/CS epilogue (L = 1) ----
    const u64 C1_2  = bcast2(1e-4f);
    const u64 C2_2  = bcast2(9e-4f);
    const u64 TWO_2 = bcast2(2.0f);
    const u64 NEG_2 = bcast2(-1.0f);

    float ssim_s = 0.0f, cs_s = 0.0f;
    #pragma unroll
    for (int j = 0; j < 2; j++) {
        u64 mu1 = acc[0][j], mu2 = acc[1][j];
        u64 mu1s = mul2(mu1, mu1);
        u64 mu2s = mul2(mu2, mu2);
        u64 mu12 = mul2(mu1, mu2);
        u64 s1  = fma2(mu1s, NEG_2, acc[2][j]);
        u64 s2  = fma2(mu2s, NEG_2, acc[3][j]);
        u64 s12 = fma2(mu12, NEG_2, acc[4][j]);
        u64 v1 = fma2(s12, TWO_2, C2_2);
        u64 v2 = add2(add2(s1, s2), C2_2);
        u64 num = mul2(fma2(mu12, TWO_2, C1_2), v1);
        u64 den = mul2(add2(add2(mu1s, mu2s), C1_2), v2);

        float n0, n1, d0, d1v, a0, a1, b0, b1;
        unpack2(num, n0, n1);
        unpack2(den, d0, d1v);
        unpack2(v1,  a0, a1);
        unpack2(v2,  b0, b1);

        int ox  = tileX + c0 + j;
        int oy0 = tileY + 2 * pr;
        if (ox < OUT) {
            if (oy0 < OUT)     { ssim_s += __fdividef(n0, d0);
                                 cs_s   += __fdividef(a0, b0); }
            if (oy0 + 1 < OUT) { ssim_s += __fdividef(n1, d1v);
                                 cs_s   += __fdividef(a1, b1); }
        }
    }

    // ---- block reduction ----
    #pragma unroll
    for (int o = 16; o > 0; o >>= 1) {
        ssim_s += __shfl_xor_sync(0xffffffffu, ssim_s, o);
        cs_s   += __shfl_xor_sync(0xffffffffu, cs_s, o);
    }
    const int wid = tid >> 5;
    if ((tid & 31) == 0) {
        red[wid * 2]     = ssim_s;
        red[wid * 2 + 1] = cs_s;
    }
    __syncthreads();
    if (tid == 0) {
        float s = 0.f, c = 0.f;
        #pragma unroll
        for (int i = 0; i < 8; i++) { s += red[i * 2]; c += red[i * 2 + 1]; }
        atomicAdd(&g_acc[2 * lev],     s);
        atomicAdd(&g_acc[2 * lev + 1], c);
    }
}

// Final scalar: prod_{l<4} mcs_l^W_l * mssim_4^(4*W_4).
__global__ void final_kernel(float* __restrict__ out) {
    const float Wt[5] = {0.0448f, 0.2856f, 0.3001f, 0.2363f, 0.1333f};
    float result = 1.0f;
    #pragma unroll
    for (int l = 0; l < 5; l++) {
        int S = 512 >> l;
        int o = S - 10;
        float cnt = (float)(NC * o * o);
        float mssim = (g_acc[2 * l]     / cnt + 1.0f) * 0.5f;
        float mcs   = (g_acc[2 * l + 1] / cnt + 1.0f) * 0.5f;
        if (l < 4) result *= powf(mcs, Wt[l]);
        else       result *= powf(mssim, 4.0f * Wt[l]);
    }
    out[0] = result;
}

extern "C" void kernel_launch(void* const* d_in, const int* in_sizes, int n_in,
                              void* d_out, int out_size)
{
    const float* img1 = (const float*)d_in[0];
    const float* img2 = (const float*)d_in[1];
    float* out = (float*)d_out;

    float* pyr1 = nullptr;
    float* pyr2 = nullptr;
    cudaGetSymbolAddress((void**)&pyr1, g_pyr1);
    cudaGetSymbolAddress((void**)&pyr2, g_pyr2);

    pyramid_kernel<<<NC * 64, 256>>>(img1, img2, pyr1, pyr2);
    ssim_all_kernel<<<16368, 256>>>(img1, img2, pyr1, pyr2);
    final_kernel<<<1, 1>>>(out);
}

// round 13
// speedup vs baseline: 1.0023x; 1.0023x over previous
#include <cuda_runtime.h>
#include <cuda_bf16.h>
#include <math.h>

// ---------------------------------------------------------------------------
// MS-SSIM, 16x3x512x512 fp32, 5 levels.
// v3b: v3 with pyramid smem pitch fixed to 68 floats (16B-aligned rows for
// float4). (1) hierarchical pyramid-build kernel, (2) single SSIM kernel for
// all 5 levels (bid-range dispatch), (3) f32x2 packed separable conv,
// launch_bounds(256,4).
// ---------------------------------------------------------------------------

#define NC 48

typedef unsigned long long u64;

// ---- f32x2 packed helpers (sm_103a) ----
__device__ __forceinline__ u64 pack2(float lo, float hi) {
    u64 r; asm("mov.b64 %0, {%1,%2};" : "=l"(r) : "f"(lo), "f"(hi)); return r;
}
__device__ __forceinline__ void unpack2(u64 v, float& lo, float& hi) {
    asm("mov.b64 {%0,%1}, %2;" : "=f"(lo), "=f"(hi) : "l"(v));
}
__device__ __forceinline__ u64 fma2(u64 a, u64 b, u64 c) {
    u64 d; asm("fma.rn.f32x2 %0, %1, %2, %3;" : "=l"(d) : "l"(a), "l"(b), "l"(c)); return d;
}
__device__ __forceinline__ u64 mul2(u64 a, u64 b) {
    u64 d; asm("mul.rn.f32x2 %0, %1, %2;" : "=l"(d) : "l"(a), "l"(b)); return d;
}
__device__ __forceinline__ u64 add2(u64 a, u64 b) {
    u64 d; asm("add.rn.f32x2 %0, %1, %2;" : "=l"(d) : "l"(a), "l"(b)); return d;
}
__device__ __forceinline__ u64 bcast2(float w) {
    unsigned u = __float_as_uint(w);
    return ((u64)u << 32) | (u64)u;
}

// Normalized 1-D Gaussian, sigma=1.5, ws=11 (symmetric: 6 distinct values).
__device__ __forceinline__ constexpr float GW(int k) {
    constexpr float g[6] = {
        0.00102838f, 0.00759873f, 0.03600081f, 0.10936079f, 0.21300570f,
        0.26601192f };
    return g[k <= 5 ? k : 10 - k];
}

// Pyramid scratch, levels 1..4, both images.
__device__ float g_pyr1[4177920];
__device__ float g_pyr2[4177920];
__device__ float g_acc[10];   // [2l]=sum(ssim), [2l+1]=sum(cs)

#define L1OFF 0
#define L2OFF 3145728      // + 48*256*256
#define L3OFF 3932160      // + 48*128*128
#define L4OFF 4128768      // + 48*64*64

// ---------------------------------------------------------------------------
// Pyramid build: each block owns one 64x64 region of one image pair and
// produces the corresponding 32x32 / 16x16 / 8x8 / 4x4 mean-pool outputs
// (iterated 2x2 means == reference's chained _avg_pool2). Grid = 48*64.
// ---------------------------------------------------------------------------
__global__ void __launch_bounds__(256) pyramid_kernel(
    const float* __restrict__ img1, const float* __restrict__ img2,
    float* __restrict__ pyr1, float* __restrict__ pyr2)
{
    // pitch 68 floats = 272 bytes (16B-aligned rows for float4 stores)
    __shared__ __align__(16) float s[2][64][68];
    __shared__ float p1[2][32][33];
    __shared__ float p2[2][16][17];
    __shared__ float p3[2][8][9];

    const int tid = threadIdx.x;
    const int bid = blockIdx.x;
    if (bid == 0 && tid < 10) g_acc[tid] = 0.0f;

    const int z  = bid >> 6;
    const int r  = bid & 63;
    const int ry = r >> 3, rx = r & 7;

    const float* b1 = img1 + (size_t)z * 512 * 512 + (size_t)ry * 64 * 512 + rx * 64;
    const float* b2 = img2 + (size_t)z * 512 * 512 + (size_t)ry * 64 * 512 + rx * 64;

    // load 64x64 region of both images (float4; gmem and smem 16B-aligned)
    #pragma unroll
    for (int it = 0; it < 4; it++) {
        int i = tid + it * 256;           // 1024 float4 per image
        int row = i >> 4, c4 = (i & 15) * 4;
        float4 v1 = *(const float4*)(b1 + (size_t)row * 512 + c4);
        float4 v2 = *(const float4*)(b2 + (size_t)row * 512 + c4);
        *(float4*)&s[0][row][c4] = v1;
        *(float4*)&s[1][row][c4] = v2;
    }
    __syncthreads();

    // level 1: 32x32
    #pragma unroll
    for (int it = 0; it < 4; it++) {
        int i = tid + it * 256;
        int oy = i >> 5, ox = i & 31;
        #pragma unroll
        for (int im = 0; im < 2; im++) {
            float v = 0.25f * ((s[im][2*oy][2*ox]   + s[im][2*oy][2*ox+1]) +
                               (s[im][2*oy+1][2*ox] + s[im][2*oy+1][2*ox+1]));
            p1[im][oy][ox] = v;
            float* dst = (im == 0 ? pyr1 : pyr2) + L1OFF;
            dst[(size_t)z * 65536 + (size_t)(ry*32 + oy) * 256 + rx*32 + ox] = v;
        }
    }
    __syncthreads();

    // level 2: 16x16
    {
        int oy = tid >> 4, ox = tid & 15;
        #pragma unroll
        for (int im = 0; im < 2; im++) {
            float v = 0.25f * ((p1[im][2*oy][2*ox]   + p1[im][2*oy][2*ox+1]) +
                               (p1[im][2*oy+1][2*ox] + p1[im][2*oy+1][2*ox+1]));
            p2[im][oy][ox] = v;
            float* dst = (im == 0 ? pyr1 : pyr2) + L2OFF;
            dst[(size_t)z * 16384 + (size_t)(ry*16 + oy) * 128 + rx*16 + ox] = v;
        }
    }
    __syncthreads();

    // level 3: 8x8
    if (tid < 64) {
        int oy = tid >> 3, ox = tid & 7;
        #pragma unroll
        for (int im = 0; im < 2; im++) {
            float v = 0.25f * ((p2[im][2*oy][2*ox]   + p2[im][2*oy][2*ox+1]) +
                               (p2[im][2*oy+1][2*ox] + p2[im][2*oy+1][2*ox+1]));
            p3[im][oy][ox] = v;
            float* dst = (im == 0 ? pyr1 : pyr2) + L3OFF;
            dst[(size_t)z * 4096 + (size_t)(ry*8 + oy) * 64 + rx*8 + ox] = v;
        }
    }
    __syncthreads();

    // level 4: 4x4
    if (tid < 16) {
        int oy = tid >> 2, ox = tid & 3;
        #pragma unroll
        for (int im = 0; im < 2; im++) {
            float v = 0.25f * ((p3[im][2*oy][2*ox]   + p3[im][2*oy][2*ox+1]) +
                               (p3[im][2*oy+1][2*ox] + p3[im][2*oy+1][2*ox+1]));
            float* dst = (im == 0 ? pyr1 : pyr2) + L4OFF;
            dst[(size_t)z * 1024 + (size_t)(ry*4 + oy) * 32 + rx*4 + ox] = v;
        }
    }
}

// ---------------------------------------------------------------------------
// SSIM for all 5 levels in one launch. 1D grid; bid range selects level.
// Blocks per level: L0 16x16x48=12288, L1 8x8x48=3072, L2 4x4x48=768,
// L3 2x2x48=192, L4 1x1x48=48. Total 16368.
// ---------------------------------------------------------------------------
__global__ void __launch_bounds__(256, 4) ssim_all_kernel(
    const float* __restrict__ img1, const float* __restrict__ img2,
    const float* __restrict__ pyr1, const float* __restrict__ pyr2)
{
    __shared__ __align__(16) float sx[42][44];
    __shared__ __align__(16) float sy[42][44];
    __shared__ __align__(16) float q[5][42][34];
    __shared__ float red[16];

    const int tid = threadIdx.x;
    const int bid = blockIdx.x;

    // ---- level dispatch ----
    const int lev = (bid >= 12288) + (bid >= 15360) + (bid >= 16128) + (bid >= 16320);
    const int base = lev == 0 ? 0 : lev == 1 ? 12288 : lev == 2 ? 15360
                   : lev == 3 ? 16128 : 16320;
    const int lsh = 4 - lev;                 // gx = 1 << lsh
    const int S = 512 >> lev;
    const int OUT = S - 10;

    const int local = bid - base;
    const int z  = local >> (2 * lsh);
    const int rem = local & ((1 << (2 * lsh)) - 1);
    const int by = rem >> lsh;
    const int bx = rem & ((1 << lsh) - 1);

    const float* xl;
    const float* yl;
    if (lev == 0)      { xl = img1;         yl = img2; }
    else if (lev == 1) { xl = pyr1 + L1OFF; yl = pyr2 + L1OFF; }
    else if (lev == 2) { xl = pyr1 + L2OFF; yl = pyr2 + L2OFF; }
    else if (lev == 3) { xl = pyr1 + L3OFF; yl = pyr2 + L3OFF; }
    else               { xl = pyr1 + L4OFF; yl = pyr2 + L4OFF; }

    const int tileX = bx * 32;
    const int tileY = by * 32;
    const float* xb = xl + (size_t)z * S * S;
    const float* yb = yl + (size_t)z * S * S;

    // ---------------- Phase A: load 42x42 tile (zero-pad OOB) -------------
    #pragma unroll
    for (int it = 0; it < 7; it++) {
        int i = tid + it * 256;
        if (i < 42 * 42) {
            int r = i / 42, c = i - r * 42;
            int gr = tileY + r, gc = tileX + c;
            float vx = 0.0f, vy = 0.0f;
            if (gr < S && gc < S) {
                vx = xb[(size_t)gr * S + gc];
                vy = yb[(size_t)gr * S + gc];
            }
            sx[r][c] = vx;
            sy[r][c] = vy;
        }
    }
    __syncthreads();

    // ---------------- Phase B: vertical conv, packed cols -----------------
    if (tid < 168) {
        const int pc = tid % 21;
        const int rb = (tid / 21) * 4;
        const int c2 = 2 * pc;

        u64 acc[5][4];
        #pragma unroll
        for (int ch = 0; ch < 5; ch++)
            #pragma unroll
            for (int i = 0; i < 4; i++) acc[ch][i] = 0ull;

        #pragma unroll
        for (int w = 0; w < 14; w++) {
            u64 xv = *(const u64*)&sx[rb + w][c2];
            u64 yv = *(const u64*)&sy[rb + w][c2];
            u64 p[5];
            p[0] = xv;
            p[1] = yv;
            p[2] = mul2(xv, xv);
            p[3] = mul2(yv, yv);
            p[4] = mul2(xv, yv);
            #pragma unroll
            for (int i = 0; i < 4; i++) {
                const int k = w - i;
                if (k >= 0 && k <= 10) {
                    const u64 g2 = bcast2(GW(k));
                    #pragma unroll
                    for (int ch = 0; ch < 5; ch++)
                        acc[ch][i] = fma2(p[ch], g2, acc[ch][i]);
                }
            }
        }
        #pragma unroll
        for (int ch = 0; ch < 5; ch++) {
            #pragma unroll
            for (int j = 0; j < 2; j++) {
                float a0lo, a0hi, a1lo, a1hi;
                unpack2(acc[ch][2*j],     a0lo, a0hi);
                unpack2(acc[ch][2*j + 1], a1lo, a1hi);
                *(u64*)&q[ch][c2    ][rb + 2*j] = pack2(a0lo, a1lo);
                *(u64*)&q[ch][c2 + 1][rb + 2*j] = pack2(a0hi, a1hi);
            }
        }
    }
    __syncthreads();

    // ---------------- Phase C: horizontal conv + epilogue -----------------
    const int pr = tid & 15;
    const int c0 = (tid >> 4) * 2;

    u64 acc[5][2];
    #pragma unroll
    for (int ch = 0; ch < 5; ch++) { acc[ch][0] = 0ull; acc[ch][1] = 0ull; }

    #pragma unroll
    for (int k = 0; k < 12; k++) {
        u64 v[5];
        #pragma unroll
        for (int ch = 0; ch < 5; ch++)
            v[ch] = *(const u64*)&q[ch][c0 + k][2 * pr];
        if (k <= 10) {
            const u64 g2 = bcast2(GW(k));
            #pragma unroll
            for (int ch = 0; ch < 5; ch++)
                acc[ch][0] = fma2(v[ch], g2, acc[ch][0]);
        }
        if (k >= 1) {
            const u64 g2 = bcast2(GW(k - 1));
            #pragma unroll
            for (int ch = 0; ch < 5; ch++)
                acc[ch][1] = fma2(v[ch], g2, acc[ch][1]);
        }
    }

    // ---- SSIM/CS epilogue (L = 1) ----
    const u64 C1_2  = bcast2(1e-4f);
    const u64 C2_2  = bcast2(9e-4f);
    const u64 TWO_2 = bcast2(2.0f);
    const u64 NEG_2 = bcast2(-1.0f);

    float ssim_s = 0.0f, cs_s = 0.0f;
    #pragma unroll
    for (int j = 0; j < 2; j++) {
        u64 mu1 = acc[0][j], mu2 = acc[1][j];
        u64 mu1s = mul2(mu1, mu1);
        u64 mu2s = mul2(mu2, mu2);
        u64 mu12 = mul2(mu1, mu2);
        u64 s1  = fma2(mu1s, NEG_2, acc[2][j]);
        u64 s2  = fma2(mu2s, NEG_2, acc[3][j]);
        u64 s12 = fma2(mu12, NEG_2, acc[4][j]);
        u64 v1 = fma2(s12, TWO_2, C2_2);
        u64 v2 = add2(add2(s1, s2), C2_2);
        u64 num = mul2(fma2(mu12, TWO_2, C1_2), v1);
        u64 den = mul2(add2(add2(mu1s, mu2s), C1_2), v2);

        float n0, n1, d0, d1v, a0, a1, b0, b1;
        unpack2(num, n0, n1);
        unpack2(den, d0, d1v);
        unpack2(v1,  a0, a1);
        unpack2(v2,  b0, b1);

        int ox  = tileX + c0 + j;
        int oy0 = tileY + 2 * pr;
        if (ox < OUT) {
            if (oy0 < OUT)     { ssim_s += __fdividef(n0, d0);
                                 cs_s   += __fdividef(a0, b0); }
            if (oy0 + 1 < OUT) { ssim_s += __fdividef(n1, d1v);
                                 cs_s   += __fdividef(a1, b1); }
        }
    }

    // ---- block reduction ----
    #pragma unroll
    for (int o = 16; o > 0; o >>= 1) {
        ssim_s += __shfl_xor_sync(0xffffffffu, ssim_s, o);
        cs_s   += __shfl_xor_sync(0xffffffffu, cs_s, o);
    }
    const int wid = tid >> 5;
    if ((tid & 31) == 0) {
        red[wid * 2]     = ssim_s;
        red[wid * 2 + 1] = cs_s;
    }
    __syncthreads();
    if (tid == 0) {
        float s = 0.f, c = 0.f;
        #pragma unroll
        for (int i = 0; i < 8; i++) { s += red[i * 2]; c += red[i * 2 + 1]; }
        atomicAdd(&g_acc[2 * lev],     s);
        atomicAdd(&g_acc[2 * lev + 1], c);
    }
}

// Final scalar: prod_{l<4} mcs_l^W_l * mssim_4^(4*W_4).
__global__ void final_kernel(float* __restrict__ out) {
    const float Wt[5] = {0.0448f, 0.2856f, 0.3001f, 0.2363f, 0.1333f};
    float result = 1.0f;
    #pragma unroll
    for (int l = 0; l < 5; l++) {
        int S = 512 >> l;
        int o = S - 10;
        float cnt = (float)(NC * o * o);
        float mssim = (g_acc[2 * l]     / cnt + 1.0f) * 0.5f;
        float mcs   = (g_acc[2 * l + 1] / cnt + 1.0f) * 0.5f;
        if (l < 4) result *= powf(mcs, Wt[l]);
        else       result *= powf(mssim, 4.0f * Wt[l]);
    }
    out[0] = result;
}

extern "C" void kernel_launch(void* const* d_in, const int* in_sizes, int n_in,
                              void* d_out, int out_size)
{
    const float* img1 = (const float*)d_in[0];
    const float* img2 = (const float*)d_in[1];
    float* out = (float*)d_out;

    float* pyr1 = nullptr;
    float* pyr2 = nullptr;
    cudaGetSymbolAddress((void**)&pyr1, g_pyr1);
    cudaGetSymbolAddress((void**)&pyr2, g_pyr2);

    pyramid_kernel<<<NC * 64, 256>>>(img1, img2, pyr1, pyr2);
    ssim_all_kernel<<<16368, 256>>>(img1, img2, pyr1, pyr2);
    final_kernel<<<1, 1>>>(out);
}